// round 13
// baseline (speedup 1.0000x reference)
#include <cuda_runtime.h>

#define NB 16384
#define NP 8
#define ND 64
#define NH 128
#define NOPS_ 37
#define OPSTART 16
#define NITER_ 16
#define NCAS 7

#define GRID_BLOCKS 740
#define XD_ROW 128             // dup x row: 64 elems x2 (contiguous rows)
#define HD_ROW 256             // dup hidden row: 128 elems x2
#define QK_STRIDE 68           // plain qkv rows
#define WARP_FLOATS 3200       // xsd 1024 + ws 2048 + scd 128
#define SMEM_BYTES (4 * WARP_FLOATS * 4)

typedef unsigned long long ull;

// ---- scratch (static device globals; no allocation) ----
__device__ int g_op[NB];
__device__ int g_carry[NB];
__device__ int g_div[NB];
__device__ int g_mod[NB];
__device__ int g_dense[NB];
__device__ int g_opcnt[NOPS_];
__device__ int g_base[NOPS_];
__device__ int g_cursor[NOPS_];
__device__ int g_cnt[4];
__device__ int g_claim[4];

__device__ __forceinline__ bool is_carry_op(int op) {
    return (op == 0) | (op == 1) | (op == 2) |
           (op == 10) | (op == 11) | (op == 12) | (op == 13);
}

__global__ void zero_kernel() {
    int t = threadIdx.x;
    if (t < NOPS_) { g_opcnt[t] = 0; g_cursor[t] = 0; }
    if (t < 4) g_claim[t] = 0;
}

// Pass 1: per-row argmax opcode; per-block smem histogram.
__global__ void route1_kernel(const float* __restrict__ x) {
    __shared__ int hist[NOPS_];
    int t = threadIdx.x;
    if (t < NOPS_) hist[t] = 0;
    __syncthreads();
    int b = blockIdx.x * blockDim.x + t;
    const float* p0 = x + (size_t)b * NP * ND + OPSTART;
    float best = p0[0];
    int op = 0;
    #pragma unroll
    for (int j = 1; j < NOPS_; j++) {
        float v = p0[j];
        if (v > best) { best = v; op = j; }   // strict > keeps first (jnp.argmax)
    }
    g_op[b] = op;
    atomicAdd(&hist[op], 1);
    __syncthreads();
    if (t < NOPS_ && hist[t] > 0) atomicAdd(&g_opcnt[t], hist[t]);
}

__global__ void scan_kernel() {
    if (threadIdx.x != 0) return;
    int cb = 0, db = 0;
    for (int op = 0; op < NOPS_; op++) {
        int c = g_opcnt[op];
        if (is_carry_op(op))          { g_base[op] = cb; cb += c; }
        else if (op == 3 || op == 4)  { g_base[op] = 0; }
        else                          { g_base[op] = db; db += c; }
    }
    g_cnt[0] = cb;
    g_cnt[1] = g_opcnt[3];
    g_cnt[2] = g_opcnt[4];
    g_cnt[3] = db;
}

// Pass 2: scatter with per-block chunk reservation.
__global__ void route2_kernel() {
    __shared__ int hist[NOPS_];
    __shared__ int bbase[NOPS_];
    __shared__ int cur[NOPS_];
    int t = threadIdx.x;
    if (t < NOPS_) { hist[t] = 0; cur[t] = 0; }
    __syncthreads();
    int b = blockIdx.x * blockDim.x + t;
    int op = g_op[b];
    atomicAdd(&hist[op], 1);
    __syncthreads();
    if (t < NOPS_ && hist[t] > 0)
        bbase[t] = atomicAdd(&g_cursor[t], hist[t]);
    __syncthreads();
    int pos = bbase[op] + atomicAdd(&cur[op], 1) + g_base[op];
    if (is_carry_op(op))  g_carry[pos] = b;
    else if (op == 3)     g_div[pos] = b;
    else if (op == 4)     g_mod[pos] = b;
    else                  g_dense[pos] = b;
}

// ---- packed fp32x2 primitives ----
__device__ __forceinline__ ull fma2(ull a, ull b, ull c) {
    ull d;
    asm("fma.rn.f32x2 %0, %1, %2, %3;" : "=l"(d) : "l"(a), "l"(b), "l"(c));
    return d;
}
__device__ __forceinline__ float2 unpack2(ull v) {
    unsigned int lo, hi;
    asm("mov.b64 {%0, %1}, %2;" : "=r"(lo), "=r"(hi) : "l"(v));
    return make_float2(__uint_as_float(lo), __uint_as_float(hi));
}

// ---------------------------------------------------------------------------
// Warp FFN on duplicated state; pack-free inner loops, 16B/lane stores.
// xsd: 8 rows x 128 floats (x duplicated); hsd: 8 rows x 256 (h duplicated).
// Layer1: lane owns h cols {lane*2,+1} in both 64-halves (accA/accB).
// Layer2: lane owns dd pair {lane*2,+1}, all 8 p rows.
// ---------------------------------------------------------------------------
__device__ __forceinline__ void ffn_w(
    float* xsd, float* hsd,
    const float* __restrict__ W1, const float* __restrict__ b1,
    const float* __restrict__ W2, const float* __restrict__ b2, int lane)
{
    const int c2 = lane * 2;
    // ---- layer 1 ----
    {
        ull accA[NP], accB[NP];
        {
            ull bA = __ldg((const ull*)(b1 + c2));
            ull bB = __ldg((const ull*)(b1 + 64 + c2));
            #pragma unroll
            for (int p = 0; p < NP; p++) { accA[p] = bA; accB[p] = bB; }
        }
        #pragma unroll 2
        for (int d4 = 0; d4 < ND; d4 += 4) {
            ull wa0 = __ldg((const ull*)(W1 + (d4 + 0) * NH + c2));
            ull wa1 = __ldg((const ull*)(W1 + (d4 + 1) * NH + c2));
            ull wa2 = __ldg((const ull*)(W1 + (d4 + 2) * NH + c2));
            ull wa3 = __ldg((const ull*)(W1 + (d4 + 3) * NH + c2));
            ull wb0 = __ldg((const ull*)(W1 + (d4 + 0) * NH + 64 + c2));
            ull wb1 = __ldg((const ull*)(W1 + (d4 + 1) * NH + 64 + c2));
            ull wb2 = __ldg((const ull*)(W1 + (d4 + 2) * NH + 64 + c2));
            ull wb3 = __ldg((const ull*)(W1 + (d4 + 3) * NH + 64 + c2));
            #pragma unroll
            for (int p = 0; p < NP; p++) {
                ulonglong2 xa = *(const ulonglong2*)&xsd[p * XD_ROW + 2 * d4];
                ulonglong2 xb = *(const ulonglong2*)&xsd[p * XD_ROW + 2 * d4 + 4];
                accA[p] = fma2(xa.x, wa0, accA[p]);
                accB[p] = fma2(xa.x, wb0, accB[p]);
                accA[p] = fma2(xa.y, wa1, accA[p]);
                accB[p] = fma2(xa.y, wb1, accB[p]);
                accA[p] = fma2(xb.x, wa2, accA[p]);
                accB[p] = fma2(xb.x, wb2, accB[p]);
                accA[p] = fma2(xb.y, wa3, accA[p]);
                accB[p] = fma2(xb.y, wb3, accB[p]);
            }
        }
        #pragma unroll
        for (int p = 0; p < NP; p++) {
            float2 a = unpack2(accA[p]), b = unpack2(accB[p]);
            float v0 = fmaxf(a.x, 0.f), v1 = fmaxf(a.y, 0.f);
            float v2 = fmaxf(b.x, 0.f), v3 = fmaxf(b.y, 0.f);
            *(float4*)&hsd[p * HD_ROW + 2 * c2]       = make_float4(v0, v0, v1, v1);
            *(float4*)&hsd[p * HD_ROW + 128 + 2 * c2] = make_float4(v2, v2, v3, v3);
        }
    }
    __syncwarp();
    // ---- layer 2 ----
    {
        ull acc[NP];
        #pragma unroll
        for (int p = 0; p < NP; p++) acc[p] = 0ull;
        #pragma unroll 2
        for (int h4 = 0; h4 < NH; h4 += 4) {
            ull w0 = __ldg((const ull*)(W2 + (h4 + 0) * ND + c2));
            ull w1 = __ldg((const ull*)(W2 + (h4 + 1) * ND + c2));
            ull w2 = __ldg((const ull*)(W2 + (h4 + 2) * ND + c2));
            ull w3 = __ldg((const ull*)(W2 + (h4 + 3) * ND + c2));
            #pragma unroll
            for (int p = 0; p < NP; p++) {
                ulonglong2 ha = *(const ulonglong2*)&hsd[p * HD_ROW + 2 * h4];
                ulonglong2 hb = *(const ulonglong2*)&hsd[p * HD_ROW + 2 * h4 + 4];
                acc[p] = fma2(ha.x, w0, acc[p]);
                acc[p] = fma2(ha.y, w1, acc[p]);
                acc[p] = fma2(hb.x, w2, acc[p]);
                acc[p] = fma2(hb.y, w3, acc[p]);
            }
        }
        float2 bf = __ldg((const float2*)(b2 + c2));
        #pragma unroll
        for (int p = 0; p < NP; p++) {
            float2 a = unpack2(acc[p]);
            float* row = &xsd[p * XD_ROW + 2 * c2];
            float4 cur = *(const float4*)row;  // (x0,x0,x1,x1)
            float v0 = cur.x + a.x + bf.x;
            float v1 = cur.z + a.y + bf.y;
            *(float4*)row = make_float4(v0, v0, v1, v1);
        }
    }
    __syncwarp();
}

// ---------------------------------------------------------------------------
// Warp carry attention on duplicated x; fused q/k/v (x LDS shared across 3
// matrices); scores stored duplicated -> pack-free s@v.
// ws: qs@0, ks@544, vs@1088 (plain, stride 68). scd: 8 x 16 dup scores.
// ---------------------------------------------------------------------------
__device__ __forceinline__ void attn_w(
    float* xsd, float* ws, float* scd,
    const float* __restrict__ Wq, const float* __restrict__ Wk,
    const float* __restrict__ Wv, int lane)
{
    const int c2 = lane * 2;
    float* qsm = ws;
    float* ksm = ws + 544;
    float* vsm = ws + 1088;
    // ---- fused q,k,v projections ----
    {
        ull aq[NP], ak[NP], av[NP];
        #pragma unroll
        for (int p = 0; p < NP; p++) { aq[p] = 0ull; ak[p] = 0ull; av[p] = 0ull; }
        #pragma unroll 2
        for (int d4 = 0; d4 < ND; d4 += 4) {
            ull wq0 = __ldg((const ull*)(Wq + (d4 + 0) * ND + c2));
            ull wq1 = __ldg((const ull*)(Wq + (d4 + 1) * ND + c2));
            ull wq2 = __ldg((const ull*)(Wq + (d4 + 2) * ND + c2));
            ull wq3 = __ldg((const ull*)(Wq + (d4 + 3) * ND + c2));
            ull wk0 = __ldg((const ull*)(Wk + (d4 + 0) * ND + c2));
            ull wk1 = __ldg((const ull*)(Wk + (d4 + 1) * ND + c2));
            ull wk2 = __ldg((const ull*)(Wk + (d4 + 2) * ND + c2));
            ull wk3 = __ldg((const ull*)(Wk + (d4 + 3) * ND + c2));
            ull wv0 = __ldg((const ull*)(Wv + (d4 + 0) * ND + c2));
            ull wv1 = __ldg((const ull*)(Wv + (d4 + 1) * ND + c2));
            ull wv2 = __ldg((const ull*)(Wv + (d4 + 2) * ND + c2));
            ull wv3 = __ldg((const ull*)(Wv + (d4 + 3) * ND + c2));
            #pragma unroll
            for (int p = 0; p < NP; p++) {
                ulonglong2 xa = *(const ulonglong2*)&xsd[p * XD_ROW + 2 * d4];
                ulonglong2 xb = *(const ulonglong2*)&xsd[p * XD_ROW + 2 * d4 + 4];
                aq[p] = fma2(xa.x, wq0, aq[p]);
                ak[p] = fma2(xa.x, wk0, ak[p]);
                av[p] = fma2(xa.x, wv0, av[p]);
                aq[p] = fma2(xa.y, wq1, aq[p]);
                ak[p] = fma2(xa.y, wk1, ak[p]);
                av[p] = fma2(xa.y, wv1, av[p]);
                aq[p] = fma2(xb.x, wq2, aq[p]);
                ak[p] = fma2(xb.x, wk2, ak[p]);
                av[p] = fma2(xb.x, wv2, av[p]);
                aq[p] = fma2(xb.y, wq3, aq[p]);
                ak[p] = fma2(xb.y, wk3, ak[p]);
                av[p] = fma2(xb.y, wv3, av[p]);
            }
        }
        #pragma unroll
        for (int p = 0; p < NP; p++) {
            float2 q = unpack2(aq[p]);
            float2 k = unpack2(ak[p]);
            float2 v = unpack2(av[p]);
            *(float2*)&qsm[p * QK_STRIDE + c2] = q;
            *(float2*)&ksm[p * QK_STRIDE + c2] = k;
            *(float2*)&vsm[p * QK_STRIDE + c2] = v;
        }
    }
    __syncwarp();
    // ---- scores (plain write into scd row slots) ----
    #pragma unroll
    for (int j = 0; j < 2; j++) {
        int idx = lane + 32 * j;
        int p = idx >> 3, qq = idx & 7;
        float s = 0.f;
        #pragma unroll
        for (int d4 = 0; d4 < ND; d4 += 4) {
            float4 qv = *(const float4*)&qsm[p * QK_STRIDE + d4];
            float4 kv = *(const float4*)&ksm[qq * QK_STRIDE + d4];
            s = fmaf(qv.x, kv.x, s); s = fmaf(qv.y, kv.y, s);
            s = fmaf(qv.z, kv.z, s); s = fmaf(qv.w, kv.w, s);
        }
        scd[p * 16 + qq] = s * 0.125f;
    }
    __syncwarp();
    // ---- softmax (lanes 0-7): read plain slots, write DUP pairs ----
    if (lane < 8) {
        float e[8];
        float m = scd[lane * 16 + 0];
        #pragma unroll
        for (int q = 1; q < 8; q++) m = fmaxf(m, scd[lane * 16 + q]);
        float sum = 0.f;
        #pragma unroll
        for (int q = 0; q < 8; q++) { e[q] = __expf(scd[lane * 16 + q] - m); sum += e[q]; }
        float inv = 1.0f / sum;
        #pragma unroll
        for (int q = 0; q < 8; q++) {
            float v = e[q] * inv;
            *(float2*)&scd[lane * 16 + 2 * q] = make_float2(v, v);
        }
    }
    __syncwarp();
    // ---- out: x += s @ v (dup s broadcast, plain v pairs, dup x RMW) ----
    {
        ull vq[8];
        #pragma unroll
        for (int q = 0; q < 8; q++)
            vq[q] = *(const ull*)&vsm[q * QK_STRIDE + c2];
        #pragma unroll
        for (int p = 0; p < NP; p++) {
            ulonglong2 s01 = *(const ulonglong2*)&scd[p * 16];
            ulonglong2 s23 = *(const ulonglong2*)&scd[p * 16 + 4];
            ulonglong2 s45 = *(const ulonglong2*)&scd[p * 16 + 8];
            ulonglong2 s67 = *(const ulonglong2*)&scd[p * 16 + 12];
            ull a = 0ull;
            a = fma2(s01.x, vq[0], a);
            a = fma2(s01.y, vq[1], a);
            a = fma2(s23.x, vq[2], a);
            a = fma2(s23.y, vq[3], a);
            a = fma2(s45.x, vq[4], a);
            a = fma2(s45.y, vq[5], a);
            a = fma2(s67.x, vq[6], a);
            a = fma2(s67.y, vq[7], a);
            float2 r = unpack2(a);
            float* row = &xsd[p * XD_ROW + 2 * c2];
            float4 cur = *(const float4*)row;
            float v0 = cur.x + r.x, v1 = cur.z + r.y;
            *(float4*)row = make_float4(v0, v0, v1, v1);
        }
    }
    __syncwarp();
}

// ---- row staging: global plain <-> SMEM duplicated (both conflict-free) ----
__device__ __forceinline__ void load_row_dup(
    float* xsd, const float* __restrict__ xrow, int lane)
{
    #pragma unroll
    for (int j = 0; j < 8; j++) {
        int f = lane + 32 * j;                       // dup float4 index 0..255
        float2 v = *(const float2*)(xrow + 2 * f);   // coalesced 8B/lane
        ((float4*)xsd)[f] = make_float4(v.x, v.x, v.y, v.y);  // 16B/lane, contiguous
    }
    __syncwarp();
}
__device__ __forceinline__ void store_row_dup(
    const float* xsd, float* __restrict__ xrow, int lane)
{
    #pragma unroll
    for (int j = 0; j < 8; j++) {
        int f = lane + 32 * j;
        float4 a = ((const float4*)xsd)[f];
        *(float2*)(xrow + 2 * f) = make_float2(a.x, a.z);
    }
    __syncwarp();
}

// ---------------------------------------------------------------------------
// ONE fused compute kernel: four work-stealing pools, heaviest first.
// ---------------------------------------------------------------------------
__global__ void __launch_bounds__(128) fused_kernel(
    const float* __restrict__ xin, float* __restrict__ xout,
    const float* __restrict__ Wi1, const float* __restrict__ bi1,
    const float* __restrict__ Wi2, const float* __restrict__ bi2,
    const float* __restrict__ Wq, const float* __restrict__ Wk,
    const float* __restrict__ Wv,
    const float* __restrict__ Wc1, const float* __restrict__ bc1,
    const float* __restrict__ Wc2, const float* __restrict__ bc2,
    const float* __restrict__ Wd1, const float* __restrict__ bd1,
    const float* __restrict__ Wd2, const float* __restrict__ bd2,
    const float* __restrict__ Wm1, const float* __restrict__ bm1,
    const float* __restrict__ Wm2, const float* __restrict__ bm2,
    const float* __restrict__ Wf1, const float* __restrict__ bf1,
    const float* __restrict__ Wf2, const float* __restrict__ bf2)
{
    extern __shared__ float smem[];
    const int w = threadIdx.x >> 5, lane = threadIdx.x & 31;
    float* xsd = smem + w * WARP_FLOATS;   // 1024: dup x state
    float* ws  = xsd + 1024;               // 2048: dup hidden / plain qkv
    float* scd = ws + 2048;                // 128: dup softmax rows

    // ---------------- pool 0: carry cascade rows ----------------
    const int n0 = g_cnt[0];
    for (;;) {
        int idx = 0;
        if (lane == 0) idx = atomicAdd(&g_claim[0], 1);
        idx = __shfl_sync(0xffffffffu, idx, 0);
        if (idx >= n0) break;
        const int b = g_carry[idx];
        const int op = g_op[b];
        load_row_dup(xsd, xin + (size_t)b * NP * ND, lane);
        ffn_w(xsd, ws, Wi1 + (size_t)op * ND * NH, bi1 + op * NH,
              Wi2 + (size_t)op * NH * ND, bi2 + op * ND, lane);
        {
            const float* W1 = Wc1 + (size_t)op * ND * NH;
            const float* B1 = bc1 + op * NH;
            const float* W2 = Wc2 + (size_t)op * NH * ND;
            const float* B2 = bc2 + op * ND;
            #pragma unroll 1
            for (int it = 0; it < NCAS; it++) {
                attn_w(xsd, ws, scd, Wq, Wk, Wv, lane);
                ffn_w(xsd, ws, W1, B1, W2, B2, lane);
            }
        }
        ffn_w(xsd, ws, Wf1 + (size_t)op * ND * NH, bf1 + op * NH,
              Wf2 + (size_t)op * NH * ND, bf2 + op * ND, lane);
        store_row_dup(xsd, xout + (size_t)b * NP * ND, lane);
    }
    // ---------------- pool 1: DIV chain rows ----------------
    const int n1 = g_cnt[1];
    for (;;) {
        int idx = 0;
        if (lane == 0) idx = atomicAdd(&g_claim[1], 1);
        idx = __shfl_sync(0xffffffffu, idx, 0);
        if (idx >= n1) break;
        const int b = g_div[idx];
        load_row_dup(xsd, xin + (size_t)b * NP * ND, lane);
        ffn_w(xsd, ws, Wi1 + (size_t)3 * ND * NH, bi1 + 3 * NH,
              Wi2 + (size_t)3 * NH * ND, bi2 + 3 * ND, lane);
        #pragma unroll 1
        for (int i = 0; i < NITER_; i++)
            ffn_w(xsd, ws, Wd1 + (size_t)i * ND * NH, bd1 + i * NH,
                  Wd2 + (size_t)i * NH * ND, bd2 + i * ND, lane);
        ffn_w(xsd, ws, Wf1 + (size_t)3 * ND * NH, bf1 + 3 * NH,
              Wf2 + (size_t)3 * NH * ND, bf2 + 3 * ND, lane);
        store_row_dup(xsd, xout + (size_t)b * NP * ND, lane);
    }
    // ---------------- pool 2: MOD chain rows ----------------
    const int n2 = g_cnt[2];
    for (;;) {
        int idx = 0;
        if (lane == 0) idx = atomicAdd(&g_claim[2], 1);
        idx = __shfl_sync(0xffffffffu, idx, 0);
        if (idx >= n2) break;
        const int b = g_mod[idx];
        load_row_dup(xsd, xin + (size_t)b * NP * ND, lane);
        ffn_w(xsd, ws, Wi1 + (size_t)4 * ND * NH, bi1 + 4 * NH,
              Wi2 + (size_t)4 * NH * ND, bi2 + 4 * ND, lane);
        #pragma unroll 1
        for (int i = 0; i < NITER_; i++)
            ffn_w(xsd, ws, Wm1 + (size_t)i * ND * NH, bm1 + i * NH,
                  Wm2 + (size_t)i * NH * ND, bm2 + i * ND, lane);
        ffn_w(xsd, ws, Wf1 + (size_t)4 * ND * NH, bf1 + 4 * NH,
              Wf2 + (size_t)4 * NH * ND, bf2 + 4 * ND, lane);
        store_row_dup(xsd, xout + (size_t)b * NP * ND, lane);
    }
    // ---------------- pool 3: dense rows (stage1 + final only) ----------------
    const int n3 = g_cnt[3];
    for (;;) {
        int idx = 0;
        if (lane == 0) idx = atomicAdd(&g_claim[3], 1);
        idx = __shfl_sync(0xffffffffu, idx, 0);
        if (idx >= n3) break;
        const int b = g_dense[idx];
        const int op = g_op[b];
        load_row_dup(xsd, xin + (size_t)b * NP * ND, lane);
        ffn_w(xsd, ws, Wi1 + (size_t)op * ND * NH, bi1 + op * NH,
              Wi2 + (size_t)op * NH * ND, bi2 + op * ND, lane);
        ffn_w(xsd, ws, Wf1 + (size_t)op * ND * NH, bf1 + op * NH,
              Wf2 + (size_t)op * NH * ND, bf2 + op * ND, lane);
        store_row_dup(xsd, xout + (size_t)b * NP * ND, lane);
    }
}

// ---------------------------------------------------------------------------
// Launch sequence (graph-capturable; scratch is static device globals).
// ---------------------------------------------------------------------------
extern "C" void kernel_launch(void* const* d_in, const int* in_sizes, int n_in,
                              void* d_out, int out_size)
{
    const float* x   = (const float*)d_in[0];
    const float* Wi1 = (const float*)d_in[1];
    const float* bi1 = (const float*)d_in[2];
    const float* Wi2 = (const float*)d_in[3];
    const float* bi2 = (const float*)d_in[4];
    const float* Wq  = (const float*)d_in[5];
    const float* Wk  = (const float*)d_in[6];
    const float* Wv  = (const float*)d_in[7];
    const float* Wc1 = (const float*)d_in[8];
    const float* bc1 = (const float*)d_in[9];
    const float* Wc2 = (const float*)d_in[10];
    const float* bc2 = (const float*)d_in[11];
    const float* Wd1 = (const float*)d_in[12];
    const float* bd1 = (const float*)d_in[13];
    const float* Wd2 = (const float*)d_in[14];
    const float* bd2 = (const float*)d_in[15];
    const float* Wm1 = (const float*)d_in[16];
    const float* bm1 = (const float*)d_in[17];
    const float* Wm2 = (const float*)d_in[18];
    const float* bm2 = (const float*)d_in[19];
    const float* Wf1 = (const float*)d_in[20];
    const float* bf1 = (const float*)d_in[21];
    const float* Wf2 = (const float*)d_in[22];
    const float* bf2 = (const float*)d_in[23];
    float* out = (float*)d_out;

    // >48KB dynamic smem opt-in (host-side attribute; not a stream op)
    cudaFuncSetAttribute(fused_kernel,
                         cudaFuncAttributeMaxDynamicSharedMemorySize,
                         SMEM_BYTES);

    zero_kernel<<<1, 64>>>();
    route1_kernel<<<NB / 128, 128>>>(x);
    scan_kernel<<<1, 32>>>();
    route2_kernel<<<NB / 128, 128>>>();
    fused_kernel<<<GRID_BLOCKS, 128, SMEM_BYTES>>>(
        x, out,
        Wi1, bi1, Wi2, bi2,
        Wq, Wk, Wv, Wc1, bc1, Wc2, bc2,
        Wd1, bd1, Wd2, bd2, Wm1, bm1, Wm2, bm2,
        Wf1, bf1, Wf2, bf2);
}

// round 14
// speedup vs baseline: 1.2735x; 1.2735x over previous
#include <cuda_runtime.h>

#define NB 16384
#define NP 8
#define ND 64
#define NH 128
#define NOPS_ 37
#define OPSTART 16
#define NITER_ 16
#define NCAS 7

#define GRID_BLOCKS 740        // R7-measured best fused config
#define WS_STRIDE 1632         // per-row workspace floats: max(8*132, 3*8*68)
#define HS_STRIDE 132          // padded hidden row
#define QK_STRIDE 68           // padded qkv row

typedef unsigned long long ull;

// ---- scratch (static device globals; no allocation) ----
__device__ int g_op[NB];
__device__ int g_carry[NB];
__device__ int g_div[NB];
__device__ int g_mod[NB];
__device__ int g_dense[NB];
__device__ int g_opcnt[NOPS_];
__device__ int g_base[NOPS_];     // per-op base within its destination list
__device__ int g_cursor[NOPS_];
__device__ int g_cnt[4];          // sizes: carry, div, mod, dense
__device__ int g_claim[4];

__device__ __forceinline__ bool is_carry_op(int op) {
    return (op == 0) | (op == 1) | (op == 2) |
           (op == 10) | (op == 11) | (op == 12) | (op == 13);
}

__global__ void zero_kernel() {
    int t = threadIdx.x;
    if (t < NOPS_) { g_opcnt[t] = 0; g_cursor[t] = 0; }
    if (t < 4) g_claim[t] = 0;
}

// Pass 1: per-row argmax opcode via vectorized LDG.128 (channels 16..52 are
// float4-aligned); per-block smem histogram -> 37 global atomics per block.
__global__ void route1_kernel(const float* __restrict__ x) {
    __shared__ int hist[NOPS_];
    int t = threadIdx.x;
    if (t < NOPS_) hist[t] = 0;
    __syncthreads();
    int b = blockIdx.x * blockDim.x + t;
    const float4* p4 = (const float4*)(x + (size_t)b * NP * ND + OPSTART);
    float v[40];
    #pragma unroll
    for (int j = 0; j < 10; j++) {
        float4 q = __ldg(&p4[j]);
        v[4 * j + 0] = q.x; v[4 * j + 1] = q.y;
        v[4 * j + 2] = q.z; v[4 * j + 3] = q.w;
    }
    float best = v[0];
    int op = 0;
    #pragma unroll
    for (int j = 1; j < NOPS_; j++) {
        if (v[j] > best) { best = v[j]; op = j; }   // strict >: first-index argmax
    }
    g_op[b] = op;
    atomicAdd(&hist[op], 1);
    __syncthreads();
    if (t < NOPS_ && hist[t] > 0) atomicAdd(&g_opcnt[t], hist[t]);
}

// Tiny scans over 37 ops: per-op bases inside each destination list.
__global__ void scan_kernel() {
    if (threadIdx.x != 0) return;
    int cb = 0, db = 0;
    for (int op = 0; op < NOPS_; op++) {
        int c = g_opcnt[op];
        if (is_carry_op(op))          { g_base[op] = cb; cb += c; }
        else if (op == 3 || op == 4)  { g_base[op] = 0; }
        else                          { g_base[op] = db; db += c; }
    }
    g_cnt[0] = cb;
    g_cnt[1] = g_opcnt[3];
    g_cnt[2] = g_opcnt[4];
    g_cnt[3] = db;
}

// Pass 2: scatter rows into op-sorted pool lists. Per-block chunk
// reservation: one global atomic per op per block, then smem-ranked scatter.
__global__ void route2_kernel() {
    __shared__ int hist[NOPS_];
    __shared__ int bbase[NOPS_];
    __shared__ int cur[NOPS_];
    int t = threadIdx.x;
    if (t < NOPS_) { hist[t] = 0; cur[t] = 0; }
    __syncthreads();
    int b = blockIdx.x * blockDim.x + t;
    int op = g_op[b];
    atomicAdd(&hist[op], 1);
    __syncthreads();
    if (t < NOPS_ && hist[t] > 0)
        bbase[t] = atomicAdd(&g_cursor[t], hist[t]);
    __syncthreads();
    int pos = bbase[op] + atomicAdd(&cur[op], 1) + g_base[op];
    if (is_carry_op(op))  g_carry[pos] = b;
    else if (op == 3)     g_div[pos] = b;
    else if (op == 4)     g_mod[pos] = b;
    else                  g_dense[pos] = b;
}

// ---- packed fp32x2 primitives (FFMA2 path; bit-identical fp32 numerics) ----
__device__ __forceinline__ ull pack2(float x, float y) {
    ull r;
    asm("mov.b64 %0, {%1, %2};"
        : "=l"(r) : "r"(__float_as_uint(x)), "r"(__float_as_uint(y)));
    return r;
}
__device__ __forceinline__ ull fma2(ull a, ull b, ull c) {
    ull d;
    asm("fma.rn.f32x2 %0, %1, %2, %3;" : "=l"(d) : "l"(a), "l"(b), "l"(c));
    return d;
}
__device__ __forceinline__ float2 unpack2(ull v) {
    unsigned int lo, hi;
    asm("mov.b64 {%0, %1}, %2;" : "=r"(lo), "=r"(hi) : "l"(v));
    return make_float2(__uint_as_float(lo), __uint_as_float(hi));
}

// ---------------------------------------------------------------------------
// Warp-level FFN with residual; one warp owns one row. (R7-proven layout:
// conflict-free 16B-stride stores, broadcast LDS reads, FFMA2 accumulators.)
// ---------------------------------------------------------------------------
__device__ __forceinline__ void ffn_w(
    float (*xs)[ND], float* ws,
    const float* __restrict__ W1, const float* __restrict__ b1,
    const float* __restrict__ W2, const float* __restrict__ b2, int lane)
{
    // ---- layer 1: h = relu(x @ W1 + b1); lane owns h columns [4*lane, +4) ----
    {
        const int h0 = lane * 4;
        float4 bb = __ldg((const float4*)(b1 + h0));
        ull acc[NP][2];
        {
            ull b01 = pack2(bb.x, bb.y), b23 = pack2(bb.z, bb.w);
            #pragma unroll
            for (int p = 0; p < NP; p++) { acc[p][0] = b01; acc[p][1] = b23; }
        }
        #pragma unroll 2
        for (int d4 = 0; d4 < ND; d4 += 4) {
            ulonglong2 w0 = __ldg((const ulonglong2*)(W1 + (d4 + 0) * NH + h0));
            ulonglong2 w1 = __ldg((const ulonglong2*)(W1 + (d4 + 1) * NH + h0));
            ulonglong2 w2 = __ldg((const ulonglong2*)(W1 + (d4 + 2) * NH + h0));
            ulonglong2 w3 = __ldg((const ulonglong2*)(W1 + (d4 + 3) * NH + h0));
            #pragma unroll
            for (int p = 0; p < NP; p++) {
                float4 xv = *(const float4*)&xs[p][d4];
                ull xx;
                xx = pack2(xv.x, xv.x);
                acc[p][0] = fma2(xx, w0.x, acc[p][0]);
                acc[p][1] = fma2(xx, w0.y, acc[p][1]);
                xx = pack2(xv.y, xv.y);
                acc[p][0] = fma2(xx, w1.x, acc[p][0]);
                acc[p][1] = fma2(xx, w1.y, acc[p][1]);
                xx = pack2(xv.z, xv.z);
                acc[p][0] = fma2(xx, w2.x, acc[p][0]);
                acc[p][1] = fma2(xx, w2.y, acc[p][1]);
                xx = pack2(xv.w, xv.w);
                acc[p][0] = fma2(xx, w3.x, acc[p][0]);
                acc[p][1] = fma2(xx, w3.y, acc[p][1]);
            }
        }
        #pragma unroll
        for (int p = 0; p < NP; p++) {
            float2 a = unpack2(acc[p][0]), b = unpack2(acc[p][1]);
            float4 o;
            o.x = fmaxf(a.x, 0.f); o.y = fmaxf(a.y, 0.f);
            o.z = fmaxf(b.x, 0.f); o.w = fmaxf(b.y, 0.f);
            *(float4*)&ws[p * HS_STRIDE + h0] = o;
        }
    }
    __syncwarp();
    // ---- layer 2: x += h @ W2 + b2; lane owns 4 dd cols, half the p rows ----
    {
        const int dd0 = (lane & 15) * 4;
        const int ph  = (lane >> 4) * 4;
        ull acc[4][2];
        #pragma unroll
        for (int i = 0; i < 4; i++) { acc[i][0] = 0ull; acc[i][1] = 0ull; }
        #pragma unroll 2
        for (int h4 = 0; h4 < NH; h4 += 4) {
            ulonglong2 w0 = __ldg((const ulonglong2*)(W2 + (h4 + 0) * ND + dd0));
            ulonglong2 w1 = __ldg((const ulonglong2*)(W2 + (h4 + 1) * ND + dd0));
            ulonglong2 w2 = __ldg((const ulonglong2*)(W2 + (h4 + 2) * ND + dd0));
            ulonglong2 w3 = __ldg((const ulonglong2*)(W2 + (h4 + 3) * ND + dd0));
            #pragma unroll
            for (int i = 0; i < 4; i++) {
                float4 hv = *(const float4*)&ws[(ph + i) * HS_STRIDE + h4];
                ull xx;
                xx = pack2(hv.x, hv.x);
                acc[i][0] = fma2(xx, w0.x, acc[i][0]);
                acc[i][1] = fma2(xx, w0.y, acc[i][1]);
                xx = pack2(hv.y, hv.y);
                acc[i][0] = fma2(xx, w1.x, acc[i][0]);
                acc[i][1] = fma2(xx, w1.y, acc[i][1]);
                xx = pack2(hv.z, hv.z);
                acc[i][0] = fma2(xx, w2.x, acc[i][0]);
                acc[i][1] = fma2(xx, w2.y, acc[i][1]);
                xx = pack2(hv.w, hv.w);
                acc[i][0] = fma2(xx, w3.x, acc[i][0]);
                acc[i][1] = fma2(xx, w3.y, acc[i][1]);
            }
        }
        float4 bb = __ldg((const float4*)(b2 + dd0));
        #pragma unroll
        for (int i = 0; i < 4; i++) {
            float2 a = unpack2(acc[i][0]), b = unpack2(acc[i][1]);
            float4 cur = *(const float4*)&xs[ph + i][dd0];
            cur.x += a.x + bb.x; cur.y += a.y + bb.y;
            cur.z += b.x + bb.z; cur.w += b.y + bb.w;
            *(float4*)&xs[ph + i][dd0] = cur;
        }
    }
    __syncwarp();
}

// ---------------------------------------------------------------------------
// Warp-level carry attention, FUSED q/k/v (packs shared across 3 matrices).
// ws layout: qs @ 0, ks @ 544, vs @ 1088, each 8 rows of stride 68.
// ---------------------------------------------------------------------------
__device__ __forceinline__ void attn_w(
    float (*xs)[ND], float* ws, float (*sc)[8],
    const float* __restrict__ Wq, const float* __restrict__ Wk,
    const float* __restrict__ Wv, int lane)
{
    const int c0 = lane * 2;
    float* qsm = ws;
    float* ksm = ws + 544;
    float* vsm = ws + 1088;
    {
        ull aq[NP], ak[NP], av[NP];
        #pragma unroll
        for (int p = 0; p < NP; p++) { aq[p] = 0ull; ak[p] = 0ull; av[p] = 0ull; }
        #pragma unroll 2
        for (int d4 = 0; d4 < ND; d4 += 4) {
            ull wq0 = __ldg((const ull*)(Wq + (d4 + 0) * ND + c0));
            ull wq1 = __ldg((const ull*)(Wq + (d4 + 1) * ND + c0));
            ull wq2 = __ldg((const ull*)(Wq + (d4 + 2) * ND + c0));
            ull wq3 = __ldg((const ull*)(Wq + (d4 + 3) * ND + c0));
            ull wk0 = __ldg((const ull*)(Wk + (d4 + 0) * ND + c0));
            ull wk1 = __ldg((const ull*)(Wk + (d4 + 1) * ND + c0));
            ull wk2 = __ldg((const ull*)(Wk + (d4 + 2) * ND + c0));
            ull wk3 = __ldg((const ull*)(Wk + (d4 + 3) * ND + c0));
            ull wv0 = __ldg((const ull*)(Wv + (d4 + 0) * ND + c0));
            ull wv1 = __ldg((const ull*)(Wv + (d4 + 1) * ND + c0));
            ull wv2 = __ldg((const ull*)(Wv + (d4 + 2) * ND + c0));
            ull wv3 = __ldg((const ull*)(Wv + (d4 + 3) * ND + c0));
            #pragma unroll
            for (int p = 0; p < NP; p++) {
                float4 xv = *(const float4*)&xs[p][d4];
                ull xx;
                xx = pack2(xv.x, xv.x);
                aq[p] = fma2(xx, wq0, aq[p]);
                ak[p] = fma2(xx, wk0, ak[p]);
                av[p] = fma2(xx, wv0, av[p]);
                xx = pack2(xv.y, xv.y);
                aq[p] = fma2(xx, wq1, aq[p]);
                ak[p] = fma2(xx, wk1, ak[p]);
                av[p] = fma2(xx, wv1, av[p]);
                xx = pack2(xv.z, xv.z);
                aq[p] = fma2(xx, wq2, aq[p]);
                ak[p] = fma2(xx, wk2, ak[p]);
                av[p] = fma2(xx, wv2, av[p]);
                xx = pack2(xv.w, xv.w);
                aq[p] = fma2(xx, wq3, aq[p]);
                ak[p] = fma2(xx, wk3, ak[p]);
                av[p] = fma2(xx, wv3, av[p]);
            }
        }
        #pragma unroll
        for (int p = 0; p < NP; p++) {
            float2 q = unpack2(aq[p]);
            float2 k = unpack2(ak[p]);
            float2 v = unpack2(av[p]);
            *(float2*)&qsm[p * QK_STRIDE + c0] = q;
            *(float2*)&ksm[p * QK_STRIDE + c0] = k;
            *(float2*)&vsm[p * QK_STRIDE + c0] = v;
        }
    }
    __syncwarp();
    // ---- scores: each lane does 2 of the 64 (p,q') dots ----
    #pragma unroll
    for (int j = 0; j < 2; j++) {
        int idx = lane + 32 * j;
        int p = idx >> 3, qq = idx & 7;
        float s = 0.f;
        #pragma unroll
        for (int d4 = 0; d4 < ND; d4 += 4) {
            float4 qv = *(const float4*)&qsm[p * QK_STRIDE + d4];
            float4 kv = *(const float4*)&ksm[qq * QK_STRIDE + d4];
            s = fmaf(qv.x, kv.x, s); s = fmaf(qv.y, kv.y, s);
            s = fmaf(qv.z, kv.z, s); s = fmaf(qv.w, kv.w, s);
        }
        sc[p][qq] = s * 0.125f;
    }
    __syncwarp();
    // ---- softmax over q' (lanes 0-7, one row each) ----
    if (lane < 8) {
        float m = sc[lane][0];
        #pragma unroll
        for (int q = 1; q < 8; q++) m = fmaxf(m, sc[lane][q]);
        float e[8], sum = 0.f;
        #pragma unroll
        for (int q = 0; q < 8; q++) { e[q] = __expf(sc[lane][q] - m); sum += e[q]; }
        float inv = 1.0f / sum;
        #pragma unroll
        for (int q = 0; q < 8; q++) sc[lane][q] = e[q] * inv;
    }
    __syncwarp();
    // ---- out: xs += s @ v (lane owns column pair c0) ----
    {
        ull vq[8];
        #pragma unroll
        for (int q = 0; q < 8; q++)
            vq[q] = *(const ull*)&vsm[q * QK_STRIDE + c0];
        #pragma unroll
        for (int p = 0; p < NP; p++) {
            float4 s0 = *(const float4*)&sc[p][0];
            float4 s1 = *(const float4*)&sc[p][4];
            ull a = 0ull;
            a = fma2(pack2(s0.x, s0.x), vq[0], a);
            a = fma2(pack2(s0.y, s0.y), vq[1], a);
            a = fma2(pack2(s0.z, s0.z), vq[2], a);
            a = fma2(pack2(s0.w, s0.w), vq[3], a);
            a = fma2(pack2(s1.x, s1.x), vq[4], a);
            a = fma2(pack2(s1.y, s1.y), vq[5], a);
            a = fma2(pack2(s1.z, s1.z), vq[6], a);
            a = fma2(pack2(s1.w, s1.w), vq[7], a);
            float2 r = unpack2(a);
            float2 cur = *(const float2*)&xs[p][c0];
            cur.x += r.x; cur.y += r.y;
            *(float2*)&xs[p][c0] = cur;
        }
    }
    __syncwarp();
}

// ---------------------------------------------------------------------------
// ONE fused compute kernel: four work-stealing pools, heaviest first.
// (R7-exact: claim 1 row per atomic in every pool.)
// ---------------------------------------------------------------------------
__global__ void __launch_bounds__(128) fused_kernel(
    const float* __restrict__ xin, float* __restrict__ xout,
    const float* __restrict__ Wi1, const float* __restrict__ bi1,
    const float* __restrict__ Wi2, const float* __restrict__ bi2,
    const float* __restrict__ Wq, const float* __restrict__ Wk,
    const float* __restrict__ Wv,
    const float* __restrict__ Wc1, const float* __restrict__ bc1,
    const float* __restrict__ Wc2, const float* __restrict__ bc2,
    const float* __restrict__ Wd1, const float* __restrict__ bd1,
    const float* __restrict__ Wd2, const float* __restrict__ bd2,
    const float* __restrict__ Wm1, const float* __restrict__ bm1,
    const float* __restrict__ Wm2, const float* __restrict__ bm2,
    const float* __restrict__ Wf1, const float* __restrict__ bf1,
    const float* __restrict__ Wf2, const float* __restrict__ bf2)
{
    __shared__ __align__(16) float xs[4][NP][ND];
    __shared__ __align__(16) float ws[4][WS_STRIDE];
    __shared__ __align__(16) float sc[4][NP][8];
    const int w = threadIdx.x >> 5, lane = threadIdx.x & 31;
    float (*xsr)[ND] = xs[w];
    float* wsr = ws[w];
    float4* mine = (float4*)&xsr[0][0];

    // ---------------- pool 0: carry cascade rows ----------------
    const int n0 = g_cnt[0];
    for (;;) {
        int idx = 0;
        if (lane == 0) idx = atomicAdd(&g_claim[0], 1);
        idx = __shfl_sync(0xffffffffu, idx, 0);
        if (idx >= n0) break;
        const int b = g_carry[idx];
        const int op = g_op[b];
        const float4* src = (const float4*)(xin + (size_t)b * NP * ND);
        #pragma unroll
        for (int j = 0; j < 4; j++) mine[lane + 32 * j] = src[lane + 32 * j];
        __syncwarp();
        ffn_w(xsr, wsr, Wi1 + (size_t)op * ND * NH, bi1 + op * NH,
              Wi2 + (size_t)op * NH * ND, bi2 + op * ND, lane);
        {
            const float* W1 = Wc1 + (size_t)op * ND * NH;
            const float* B1 = bc1 + op * NH;
            const float* W2 = Wc2 + (size_t)op * NH * ND;
            const float* B2 = bc2 + op * ND;
            #pragma unroll 1
            for (int it = 0; it < NCAS; it++) {
                attn_w(xsr, wsr, sc[w], Wq, Wk, Wv, lane);
                ffn_w(xsr, wsr, W1, B1, W2, B2, lane);
            }
        }
        ffn_w(xsr, wsr, Wf1 + (size_t)op * ND * NH, bf1 + op * NH,
              Wf2 + (size_t)op * NH * ND, bf2 + op * ND, lane);
        float4* dst = (float4*)(xout + (size_t)b * NP * ND);
        #pragma unroll
        for (int j = 0; j < 4; j++) dst[lane + 32 * j] = mine[lane + 32 * j];
        __syncwarp();
    }
    // ---------------- pool 1: DIV chain rows ----------------
    const int n1 = g_cnt[1];
    for (;;) {
        int idx = 0;
        if (lane == 0) idx = atomicAdd(&g_claim[1], 1);
        idx = __shfl_sync(0xffffffffu, idx, 0);
        if (idx >= n1) break;
        const int b = g_div[idx];
        const float4* src = (const float4*)(xin + (size_t)b * NP * ND);
        #pragma unroll
        for (int j = 0; j < 4; j++) mine[lane + 32 * j] = src[lane + 32 * j];
        __syncwarp();
        ffn_w(xsr, wsr, Wi1 + (size_t)3 * ND * NH, bi1 + 3 * NH,
              Wi2 + (size_t)3 * NH * ND, bi2 + 3 * ND, lane);
        #pragma unroll 1
        for (int i = 0; i < NITER_; i++)
            ffn_w(xsr, wsr, Wd1 + (size_t)i * ND * NH, bd1 + i * NH,
                  Wd2 + (size_t)i * NH * ND, bd2 + i * ND, lane);
        ffn_w(xsr, wsr, Wf1 + (size_t)3 * ND * NH, bf1 + 3 * NH,
              Wf2 + (size_t)3 * NH * ND, bf2 + 3 * ND, lane);
        float4* dst = (float4*)(xout + (size_t)b * NP * ND);
        #pragma unroll
        for (int j = 0; j < 4; j++) dst[lane + 32 * j] = mine[lane + 32 * j];
        __syncwarp();
    }
    // ---------------- pool 2: MOD chain rows ----------------
    const int n2 = g_cnt[2];
    for (;;) {
        int idx = 0;
        if (lane == 0) idx = atomicAdd(&g_claim[2], 1);
        idx = __shfl_sync(0xffffffffu, idx, 0);
        if (idx >= n2) break;
        const int b = g_mod[idx];
        const float4* src = (const float4*)(xin + (size_t)b * NP * ND);
        #pragma unroll
        for (int j = 0; j < 4; j++) mine[lane + 32 * j] = src[lane + 32 * j];
        __syncwarp();
        ffn_w(xsr, wsr, Wi1 + (size_t)4 * ND * NH, bi1 + 4 * NH,
              Wi2 + (size_t)4 * NH * ND, bi2 + 4 * ND, lane);
        #pragma unroll 1
        for (int i = 0; i < NITER_; i++)
            ffn_w(xsr, wsr, Wm1 + (size_t)i * ND * NH, bm1 + i * NH,
                  Wm2 + (size_t)i * NH * ND, bm2 + i * ND, lane);
        ffn_w(xsr, wsr, Wf1 + (size_t)4 * ND * NH, bf1 + 4 * NH,
              Wf2 + (size_t)4 * NH * ND, bf2 + 4 * ND, lane);
        float4* dst = (float4*)(xout + (size_t)b * NP * ND);
        #pragma unroll
        for (int j = 0; j < 4; j++) dst[lane + 32 * j] = mine[lane + 32 * j];
        __syncwarp();
    }
    // ---------------- pool 3: dense rows (stage1 + final only) ----------------
    const int n3 = g_cnt[3];
    for (;;) {
        int idx = 0;
        if (lane == 0) idx = atomicAdd(&g_claim[3], 1);
        idx = __shfl_sync(0xffffffffu, idx, 0);
        if (idx >= n3) break;
        const int b = g_dense[idx];
        const int op = g_op[b];
        const float4* src = (const float4*)(xin + (size_t)b * NP * ND);
        #pragma unroll
        for (int j = 0; j < 4; j++) mine[lane + 32 * j] = src[lane + 32 * j];
        __syncwarp();
        ffn_w(xsr, wsr, Wi1 + (size_t)op * ND * NH, bi1 + op * NH,
              Wi2 + (size_t)op * NH * ND, bi2 + op * ND, lane);
        ffn_w(xsr, wsr, Wf1 + (size_t)op * ND * NH, bf1 + op * NH,
              Wf2 + (size_t)op * NH * ND, bf2 + op * ND, lane);
        float4* dst = (float4*)(xout + (size_t)b * NP * ND);
        #pragma unroll
        for (int j = 0; j < 4; j++) dst[lane + 32 * j] = mine[lane + 32 * j];
        __syncwarp();
    }
}

// ---------------------------------------------------------------------------
// Launch sequence (graph-capturable; scratch is static device globals).
// ---------------------------------------------------------------------------
extern "C" void kernel_launch(void* const* d_in, const int* in_sizes, int n_in,
                              void* d_out, int out_size)
{
    const float* x   = (const float*)d_in[0];
    const float* Wi1 = (const float*)d_in[1];
    const float* bi1 = (const float*)d_in[2];
    const float* Wi2 = (const float*)d_in[3];
    const float* bi2 = (const float*)d_in[4];
    const float* Wq  = (const float*)d_in[5];
    const float* Wk  = (const float*)d_in[6];
    const float* Wv  = (const float*)d_in[7];
    const float* Wc1 = (const float*)d_in[8];
    const float* bc1 = (const float*)d_in[9];
    const float* Wc2 = (const float*)d_in[10];
    const float* bc2 = (const float*)d_in[11];
    const float* Wd1 = (const float*)d_in[12];
    const float* bd1 = (const float*)d_in[13];
    const float* Wd2 = (const float*)d_in[14];
    const float* bd2 = (const float*)d_in[15];
    const float* Wm1 = (const float*)d_in[16];
    const float* bm1 = (const float*)d_in[17];
    const float* Wm2 = (const float*)d_in[18];
    const float* bm2 = (const float*)d_in[19];
    const float* Wf1 = (const float*)d_in[20];
    const float* bf1 = (const float*)d_in[21];
    const float* Wf2 = (const float*)d_in[22];
    const float* bf2 = (const float*)d_in[23];
    float* out = (float*)d_out;

    zero_kernel<<<1, 64>>>();
    route1_kernel<<<NB / 128, 128>>>(x);
    scan_kernel<<<1, 32>>>();
    route2_kernel<<<NB / 128, 128>>>();
    fused_kernel<<<GRID_BLOCKS, 128>>>(
        x, out,
        Wi1, bi1, Wi2, bi2,
        Wq, Wk, Wv, Wc1, bc1, Wc2, bc2,
        Wd1, bd1, Wd2, bd2, Wm1, bm1, Wm2, bm2,
        Wf1, bf1, Wf2, bf2);
}